// round 9
// baseline (speedup 1.0000x reference)
#include <cuda_runtime.h>
#include <cuda_bf16.h>

// Skipgram negative-sampling loss — ONE launch.
// Grid-wide reduction via a single packed u64 atomic (bit-deterministic).
// Row gathers use LDG.64 (float2/lane) instead of LDG.128: one LDG.128 spans
// 4 cache lines whose wavefronts replay at ~2.07 cyc/wf inside the L1tex
// pipe; LDG.64 spans 2 lines (~3.07 cyc/LDG total), cutting per-sample L1tex
// occupancy from ~99 to ~74 cyc (R8 showed L1tex replay is the binding pipe).
//
// Inputs (metadata order):
//   d_in[0] input_idx  int32  [N]
//   d_in[1] output_idx int32  [N]
//   d_in[2] neg_idx    int32  [N, K]
//   d_in[3] W_in       fp32   [N_WORDS, D]
//   d_in[4] W_out      fp32   [N_WORDS, D]
// Output: scalar fp32 loss.

#define N_SAMPLES 65536
#define DIMS      128
#define KNEG      10
#define NROWS     (KNEG + 1)      // 11 W_out rows per sample
#define WARPS_PER_BLOCK 8
#define NBLOCKS   (N_SAMPLES / WARPS_PER_BLOCK)   // 8192
#define NTHREADS  (WARPS_PER_BLOCK * 32)          // 256

#define FP_BIAS   8192.0          // block partial is in (-8192, 0]
#define FP_SCALE  1048576.0       // 2^20

__device__ unsigned long long g_acc_pack;   // zero-initialized

struct Row { float2 lo, hi; };    // lane's 4 floats of a 128-float row

__device__ __forceinline__ float warp_sum(float v) {
#pragma unroll
    for (int o = 16; o > 0; o >>= 1)
        v += __shfl_xor_sync(0xffffffff, v, o);
    return v;
}

// fast log(sigmoid(x)) = -log(1 + exp(-x)); safe for |x| << 80, rel err ~2^-21
__device__ __forceinline__ float logsig_fast(float x) {
    return -__logf(1.0f + __expf(-x));
}

// cache policy: keep table lines resident in L2
__device__ __forceinline__ unsigned long long make_keep_policy() {
    unsigned long long pol;
    asm("createpolicy.fractional.L2::evict_last.b64 %0, 1.0;" : "=l"(pol));
    return pol;
}

// read-only float2 load with L2 keep-resident policy (LDG.64 -> 2 lines/LDG)
__device__ __forceinline__ float2 ldg2(const float* p, unsigned long long pol) {
    float2 v;
    asm("ld.global.nc.L2::cache_hint.v2.f32 {%0,%1}, [%2], %3;"
        : "=f"(v.x), "=f"(v.y) : "l"(p), "l"(pol));
    return v;
}

// gather this lane's two float2 chunks of a 128-float row
__device__ __forceinline__ Row load_row(const float* base, int lane,
                                        unsigned long long pol) {
    Row r;
    r.lo = ldg2(base + 2 * lane, pol);          // floats [0,64)
    r.hi = ldg2(base + 64 + 2 * lane, pol);     // floats [64,128)
    return r;
}

__device__ __forceinline__ float dot_row(const Row& a, const Row& b) {
    return a.lo.x * b.lo.x + a.lo.y * b.lo.y + a.hi.x * b.hi.x + a.hi.y * b.hi.y;
}

__global__ __launch_bounds__(NTHREADS, 6)
void sg_compute_kernel(const int* __restrict__ input_idx,
                       const int* __restrict__ output_idx,
                       const int* __restrict__ neg_idx,
                       const float* __restrict__ W_in,
                       const float* __restrict__ W_out,
                       float* __restrict__ out) {
    const int warp = threadIdx.x >> 5;
    const int lane = threadIdx.x & 31;
    const int n = blockIdx.x * WARPS_PER_BLOCK + warp;

    const unsigned long long pol = make_keep_policy();

    // --- independent scalar index loads (uniform across warp, issue early) ---
    int idx[NROWS];
    idx[0] = output_idx[n];
#pragma unroll
    for (int k = 0; k < KNEG; k++)
        idx[k + 1] = neg_idx[n * KNEG + k];
    const int ii = input_idx[n];

    // --- input row ---
    Row a = load_row(W_in + (size_t)ii * DIMS, lane, pol);

    // --- 3-deep rotated streaming of the 11 W_out rows ---
    Row b0 = load_row(W_out + (size_t)idx[0] * DIMS, lane, pol);
    Row b1 = load_row(W_out + (size_t)idx[1] * DIMS, lane, pol);
    Row b2 = load_row(W_out + (size_t)idx[2] * DIMS, lane, pol);

    float local = 0.0f;
#pragma unroll
    for (int j = 0; j < NROWS; j++) {
        float p = dot_row(a, b0);
        // rotate pipeline; issue next load before the reduction chain
        b0 = b1;
        b1 = b2;
        if (j + 3 < NROWS)
            b2 = load_row(W_out + (size_t)idx[j + 3] * DIMS, lane, pol);
        float d = warp_sum(p);
        // all lanes compute redundantly (same warp-issue cost, no predication)
        local += logsig_fast(j == 0 ? d : -d);
    }

    // --- block reduce ---
    __shared__ float s[WARPS_PER_BLOCK];
    if (lane == 0) s[warp] = local;
    __syncthreads();
    if (threadIdx.x == 0) {
        float t = 0.0f;
#pragma unroll
        for (int i = 0; i < WARPS_PER_BLOCK; i++) t += s[i];

        // fixed-point pack: value in [0, 2^34), counter at bit 48
        long long fixed = __double2ll_rn(((double)t + FP_BIAS) * FP_SCALE);
        unsigned long long add = (1ULL << 48) + (unsigned long long)fixed;
        unsigned long long old = atomicAdd(&g_acc_pack, add);

        if ((old >> 48) == NBLOCKS - 1) {
            // This block is last: old + add is the complete packed total.
            unsigned long long total = old + add;
            double sum = (double)(long long)(total & ((1ULL << 48) - 1)) / FP_SCALE
                         - (double)NBLOCKS * FP_BIAS;
            out[0] = (float)(sum / (double)N_SAMPLES);
            g_acc_pack = 0ULL;   // reset for next graph replay (no racers remain)
        }
    }
}

extern "C" void kernel_launch(void* const* d_in, const int* in_sizes, int n_in,
                              void* d_out, int out_size) {
    const int*   input_idx  = (const int*)d_in[0];
    const int*   output_idx = (const int*)d_in[1];
    const int*   neg_idx    = (const int*)d_in[2];
    const float* W_in       = (const float*)d_in[3];
    const float* W_out      = (const float*)d_in[4];
    float* out = (float*)d_out;

    sg_compute_kernel<<<NBLOCKS, NTHREADS>>>(
        input_idx, output_idx, neg_idx, W_in, W_out, out);
}

// round 11
// speedup vs baseline: 1.4902x; 1.4902x over previous
#include <cuda_runtime.h>
#include <cuda_bf16.h>

// Skipgram negative-sampling loss — ONE launch.
// Grid-wide reduction via a single packed u64 atomic (bit-deterministic):
//   bits [0:48)  fixed-point sum of block partials (bias 8192, scale 2^20)
//   bits [48:64) block-completion counter
//
// R9 A/B proved LDG.128 >> LDG.64 for the row gathers (per-LDG overhead
// dominates) -> back to float4/lane rows. New in R10: all 96 per-block
// indices are staged through shared by coalesced loads (3-4 L1tex wavefronts
// per block instead of 96 broadcast wavefronts from per-warp scalar loads),
// and the freed registers buy 7 blocks/SM of occupancy.
//
// Inputs (metadata order):
//   d_in[0] input_idx  int32  [N]
//   d_in[1] output_idx int32  [N]
//   d_in[2] neg_idx    int32  [N, K]
//   d_in[3] W_in       fp32   [N_WORDS, D]
//   d_in[4] W_out      fp32   [N_WORDS, D]
// Output: scalar fp32 loss.

#define N_SAMPLES 65536
#define DIMS      128
#define KNEG      10
#define NROWS     (KNEG + 1)      // 11 W_out rows per sample
#define WARPS_PER_BLOCK 8
#define NBLOCKS   (N_SAMPLES / WARPS_PER_BLOCK)   // 8192
#define NTHREADS  (WARPS_PER_BLOCK * 32)          // 256

#define FP_BIAS   8192.0          // block partial is in (-8192, 0]
#define FP_SCALE  1048576.0       // 2^20

__device__ unsigned long long g_acc_pack;   // zero-initialized

__device__ __forceinline__ float warp_sum(float v) {
#pragma unroll
    for (int o = 16; o > 0; o >>= 1)
        v += __shfl_xor_sync(0xffffffff, v, o);
    return v;
}

// fast log(sigmoid(x)) = -log(1 + exp(-x)); safe for |x| << 80, rel err ~2^-21
__device__ __forceinline__ float logsig_fast(float x) {
    return -__logf(1.0f + __expf(-x));
}

__device__ __forceinline__ float dot4(float4 a, float4 b) {
    return a.x * b.x + a.y * b.y + a.z * b.z + a.w * b.w;
}

// cache policy: keep table lines resident in L2
__device__ __forceinline__ unsigned long long make_keep_policy() {
    unsigned long long pol;
    asm("createpolicy.fractional.L2::evict_last.b64 %0, 1.0;" : "=l"(pol));
    return pol;
}

// read-only float4 load with L2 keep-resident policy (LDG.128)
__device__ __forceinline__ float4 ldg_keep(const float4* p, unsigned long long pol) {
    float4 v;
    asm("ld.global.nc.L2::cache_hint.v4.f32 {%0,%1,%2,%3}, [%4], %5;"
        : "=f"(v.x), "=f"(v.y), "=f"(v.z), "=f"(v.w) : "l"(p), "l"(pol));
    return v;
}

__global__ __launch_bounds__(NTHREADS, 7)
void sg_compute_kernel(const int* __restrict__ input_idx,
                       const int* __restrict__ output_idx,
                       const int* __restrict__ neg_idx,
                       const float* __restrict__ W_in,
                       const float* __restrict__ W_out,
                       float* __restrict__ out) {
    const int tid  = threadIdx.x;
    const int warp = tid >> 5;
    const int lane = tid & 31;
    const int nbase = blockIdx.x * WARPS_PER_BLOCK;

    const unsigned long long pol = make_keep_policy();

    // --- stage the block's 96 indices through shared (coalesced loads) ---
    // layout: s_idx[w][0] = input idx, s_idx[w][1+j] = j-th W_out row (0=pos)
    __shared__ int s_idx[WARPS_PER_BLOCK][NROWS + 1];
    if (tid < WARPS_PER_BLOCK) {
        s_idx[tid][0] = input_idx[nbase + tid];
        s_idx[tid][1] = output_idx[nbase + tid];
    }
    if (tid < WARPS_PER_BLOCK * KNEG) {            // 80 consecutive ints
        int w = tid / KNEG, k = tid % KNEG;
        s_idx[w][2 + k] = neg_idx[nbase * KNEG + tid];
    }
    __syncthreads();

    // --- input row: each lane holds one float4 of the 128-float row ---
    float4 a = ldg_keep(reinterpret_cast<const float4*>(
                   W_in + (size_t)s_idx[warp][0] * DIMS) + lane, pol);

    // --- 3-deep rotated streaming of the 11 W_out rows ---
    float4 b0 = ldg_keep(reinterpret_cast<const float4*>(
                    W_out + (size_t)s_idx[warp][1] * DIMS) + lane, pol);
    float4 b1 = ldg_keep(reinterpret_cast<const float4*>(
                    W_out + (size_t)s_idx[warp][2] * DIMS) + lane, pol);
    float4 b2 = ldg_keep(reinterpret_cast<const float4*>(
                    W_out + (size_t)s_idx[warp][3] * DIMS) + lane, pol);

    float local = 0.0f;
#pragma unroll
    for (int j = 0; j < NROWS; j++) {
        float p = dot4(a, b0);
        // rotate pipeline; issue next load before the reduction chain
        b0 = b1;
        b1 = b2;
        if (j + 3 < NROWS)
            b2 = ldg_keep(reinterpret_cast<const float4*>(
                     W_out + (size_t)s_idx[warp][1 + j + 3] * DIMS) + lane, pol);
        float d = warp_sum(p);
        // all lanes compute redundantly (same warp-issue cost, no predication)
        local += logsig_fast(j == 0 ? d : -d);
    }

    // --- block reduce ---
    __shared__ float s[WARPS_PER_BLOCK];
    if (lane == 0) s[warp] = local;
    __syncthreads();
    if (tid == 0) {
        float t = 0.0f;
#pragma unroll
        for (int i = 0; i < WARPS_PER_BLOCK; i++) t += s[i];

        // fixed-point pack: value in [0, 2^34), counter at bit 48
        long long fixed = __double2ll_rn(((double)t + FP_BIAS) * FP_SCALE);
        unsigned long long add = (1ULL << 48) + (unsigned long long)fixed;
        unsigned long long old = atomicAdd(&g_acc_pack, add);

        if ((old >> 48) == NBLOCKS - 1) {
            // This block is last: old + add is the complete packed total.
            unsigned long long total = old + add;
            double sum = (double)(long long)(total & ((1ULL << 48) - 1)) / FP_SCALE
                         - (double)NBLOCKS * FP_BIAS;
            out[0] = (float)(sum / (double)N_SAMPLES);
            g_acc_pack = 0ULL;   // reset for next graph replay (no racers remain)
        }
    }
}

extern "C" void kernel_launch(void* const* d_in, const int* in_sizes, int n_in,
                              void* d_out, int out_size) {
    const int*   input_idx  = (const int*)d_in[0];
    const int*   output_idx = (const int*)d_in[1];
    const int*   neg_idx    = (const int*)d_in[2];
    const float* W_in       = (const float*)d_in[3];
    const float* W_out      = (const float*)d_in[4];
    float* out = (float*)d_out;

    sg_compute_kernel<<<NBLOCKS, NTHREADS>>>(
        input_idx, output_idx, neg_idx, W_in, W_out, out);
}